// round 3
// baseline (speedup 1.0000x reference)
#include <cuda_runtime.h>

// Problem constants
#define NB 2
#define LB 1024
#define EB 256
#define HB 8
#define PB 4
#define KK 4
#define DB 32
#define MROWS (NB*LB)        // 2048
#define NH (NB*HB)           // 16
#define QPB (LB*PB)          // 4096 queries per batch-head
#define QTOT (NH*QPB)        // 65536
#define GD 10                // grid cells per axis
#define NCELL (GD*GD*GD)     // 1000

// ---------------- scratch (device globals) ---------------------------------
__device__ float  g_val [MROWS*EB];
__device__ float  g_off [MROWS*96];
__device__ float  g_attn[MROWS*32];
__device__ float  g_attw[QTOT];
__device__ float4 g_sl  [QTOT];             // sampling loc (x,y,z,|s|^2)
__device__ int    g_key [QTOT];             // cell id per query
__device__ int    g_qperm[QTOT];            // per-b permutation (sorted by cell)
__device__ float4 g_refPts[NB][LB];         // cell-sorted refs (x,y,z,|r|^2)
__device__ int    g_refIdx[NB][LB];         // original ref index
__device__ int    g_cellStart[NB][NCELL+1];
__device__ int    g_idx [QTOT*KK];
__device__ float  g_w   [QTOT*KK];
__device__ float  g_A   [MROWS*EB];

// ---------------- generic 64x64 tiled SGEMM with bias ----------------------
__device__ __forceinline__ void sgemm256_body(const float* __restrict__ A,
                                              const float* __restrict__ B,
                                              const float* __restrict__ bias,
                                              float* __restrict__ C) {
    const int K = 256, NC = 256;
    __shared__ float As[16][64];
    __shared__ float Bs[16][68];
    const int tid = threadIdx.x;
    const int tx = tid & 15, ty = tid >> 4;
    const int rowBase = blockIdx.y * 64;
    const int colBase = blockIdx.x * 64;
    float acc[4][4];
    #pragma unroll
    for (int i = 0; i < 4; i++)
        #pragma unroll
        for (int j = 0; j < 4; j++) acc[i][j] = 0.f;

    for (int k0 = 0; k0 < K; k0 += 16) {
        #pragma unroll
        for (int i = 0; i < 4; i++) {
            int idx = tid + i*256;
            int m = idx >> 4, k = idx & 15;
            As[k][m] = A[(rowBase + m)*K + k0 + k];
        }
        #pragma unroll
        for (int i = 0; i < 4; i++) {
            int idx = tid + i*256;
            int k = idx >> 6, n = idx & 63;
            Bs[k][n] = B[(k0 + k)*NC + colBase + n];
        }
        __syncthreads();
        #pragma unroll
        for (int kk = 0; kk < 16; kk++) {
            float4 av = *(const float4*)&As[kk][ty*4];
            float4 bv = *(const float4*)&Bs[kk][tx*4];
            float a[4] = {av.x, av.y, av.z, av.w};
            float b[4] = {bv.x, bv.y, bv.z, bv.w};
            #pragma unroll
            for (int i = 0; i < 4; i++)
                #pragma unroll
                for (int j = 0; j < 4; j++)
                    acc[i][j] = fmaf(a[i], b[j], acc[i][j]);
        }
        __syncthreads();
    }
    #pragma unroll
    for (int i = 0; i < 4; i++) {
        int gm = rowBase + ty*4 + i;
        #pragma unroll
        for (int j = 0; j < 4; j++) {
            int gn = colBase + tx*4 + j;
            C[gm*NC + gn] = acc[i][j] + bias[gn];
        }
    }
}

__global__ void gemm_val_k(const float* A, const float* B, const float* bias) {
    sgemm256_body(A, B, bias, g_val);
}
__global__ void gemm_out_k(const float* B, const float* bias, float* C) {
    sgemm256_body(g_A, B, bias, C);
}

// Merged off(96) + attn(32) projection: 128 virtual columns
__global__ void gemm_oa_k(const float* __restrict__ A,
                          const float* __restrict__ W_off,  const float* __restrict__ b_off,
                          const float* __restrict__ W_attn, const float* __restrict__ b_attn) {
    const int K = 256;
    __shared__ float As[16][64];
    __shared__ float Bs[16][68];
    const int tid = threadIdx.x;
    const int tx = tid & 15, ty = tid >> 4;
    const int rowBase = blockIdx.y * 64;
    const int colBase = blockIdx.x * 64;
    float acc[4][4];
    #pragma unroll
    for (int i = 0; i < 4; i++)
        #pragma unroll
        for (int j = 0; j < 4; j++) acc[i][j] = 0.f;

    for (int k0 = 0; k0 < K; k0 += 16) {
        #pragma unroll
        for (int i = 0; i < 4; i++) {
            int idx = tid + i*256;
            int m = idx >> 4, k = idx & 15;
            As[k][m] = A[(rowBase + m)*K + k0 + k];
        }
        #pragma unroll
        for (int i = 0; i < 4; i++) {
            int idx = tid + i*256;
            int k = idx >> 6, n = idx & 63;
            int gn = colBase + n;
            int gk = k0 + k;
            Bs[k][n] = (gn < 96) ? W_off[gk*96 + gn] : W_attn[gk*32 + (gn - 96)];
        }
        __syncthreads();
        #pragma unroll
        for (int kk = 0; kk < 16; kk++) {
            float4 av = *(const float4*)&As[kk][ty*4];
            float4 bv = *(const float4*)&Bs[kk][tx*4];
            float a[4] = {av.x, av.y, av.z, av.w};
            float b[4] = {bv.x, bv.y, bv.z, bv.w};
            #pragma unroll
            for (int i = 0; i < 4; i++)
                #pragma unroll
                for (int j = 0; j < 4; j++)
                    acc[i][j] = fmaf(a[i], b[j], acc[i][j]);
        }
        __syncthreads();
    }
    #pragma unroll
    for (int i = 0; i < 4; i++) {
        int gm = rowBase + ty*4 + i;
        #pragma unroll
        for (int j = 0; j < 4; j++) {
            int gn = colBase + tx*4 + j;
            if (gn < 96) g_off[gm*96 + gn]         = acc[i][j] + b_off[gn];
            else         g_attn[gm*32 + (gn - 96)] = acc[i][j] + b_attn[gn - 96];
        }
    }
}

// ---------------- inclusive scan over 1024 smem ints, 256 threads ----------
__device__ __forceinline__ void inclusive1024(int* a, int* b, int tid) {
    int* src = a; int* dst = b;
    #pragma unroll
    for (int off = 1; off < 1024; off <<= 1) {
        #pragma unroll
        for (int j = 0; j < 4; j++) {
            int i = tid + j*256;
            int v = src[i];
            if (i >= off) v += src[i - off];
            dst[i] = v;
        }
        __syncthreads();
        int* t = src; src = dst; dst = t;
    }
    // 10 swaps -> result back in a
}

__device__ __forceinline__ int cellClamp(float v) {
    int c = (int)floorf(v * (float)GD);
    return min(max(c, 0), GD - 1);
}

// ---------------- prep (softmax + sampling locs + keys) + grid build -------
// blocks 0..255: one thread per query. blocks 256,257: build ref grid for n.
__global__ void prep_k(const float* __restrict__ rp) {
    __shared__ int sA[1024];
    __shared__ int sB[1024];
    const int tid = threadIdx.x;
    const int blk = blockIdx.x;

    if (blk >= 256) {
        // ---- grid build for batch n ----
        const int n = blk - 256;
        const float* rpb = rp + n*LB*3;
        for (int i = tid; i < 1024; i += 256) sA[i] = 0;
        __syncthreads();
        #pragma unroll
        for (int j = 0; j < 4; j++) {
            int i = tid + j*256;
            float x = rpb[3*i], y = rpb[3*i+1], z = rpb[3*i+2];
            int key = (cellClamp(z)*GD + cellClamp(y))*GD + cellClamp(x);
            atomicAdd(&sA[key], 1);
        }
        __syncthreads();
        inclusive1024(sA, sB, tid);
        // write exclusive starts
        for (int i = tid; i <= NCELL; i += 256)
            g_cellStart[n][i] = (i == 0) ? 0 : sA[i-1];
        for (int i = tid; i < 1024; i += 256)
            sB[i] = (i == 0) ? 0 : sA[i-1];
        __syncthreads();
        #pragma unroll
        for (int j = 0; j < 4; j++) {
            int i = tid + j*256;
            float x = rpb[3*i], y = rpb[3*i+1], z = rpb[3*i+2];
            int key = (cellClamp(z)*GD + cellClamp(y))*GD + cellClamp(x);
            int slot = atomicAdd(&sB[key], 1);
            g_refPts[n][slot] = make_float4(x, y, z, x*x + y*y + z*z);
            g_refIdx[n][slot] = i;
        }
        return;
    }

    // ---- query prep ----
    const int q = blk*256 + tid;
    const int b = q >> 12;
    const int qi = q & (QPB - 1);
    const int l = qi >> 2, p = qi & 3;
    const int n = b >> 3, h = b & 7;
    const int m = n*LB + l;

    float x = g_attn[m*32 + h*4 + p];
    float mx = x;
    mx = fmaxf(mx, __shfl_xor_sync(0xffffffffu, mx, 1));
    mx = fmaxf(mx, __shfl_xor_sync(0xffffffffu, mx, 2));
    float e = expf(x - mx);
    float se = e;
    se += __shfl_xor_sync(0xffffffffu, se, 1);
    se += __shfl_xor_sync(0xffffffffu, se, 2);
    g_attw[q] = e / se;

    float rx = rp[m*3], ry = rp[m*3+1], rz = rp[m*3+2];
    const float* of = g_off + m*96 + h*12 + p*3;
    float sx = rx + of[0], sy = ry + of[1], sz = rz + of[2];
    g_sl[q] = make_float4(sx, sy, sz, sx*sx + sy*sy + sz*sz);
    g_key[q] = (cellClamp(sz)*GD + cellClamp(sy))*GD + cellClamp(sx);
}

// ---------------- per-b counting sort of 4096 queries by cell --------------
__global__ void sortq_k() {
    __shared__ int sA[1024];
    __shared__ int sB[1024];
    const int b = blockIdx.x, tid = threadIdx.x;
    for (int i = tid; i < 1024; i += 256) sA[i] = 0;
    __syncthreads();
    #pragma unroll
    for (int j = 0; j < 16; j++) {
        int qi = tid + j*256;
        atomicAdd(&sA[g_key[b*QPB + qi]], 1);
    }
    __syncthreads();
    inclusive1024(sA, sB, tid);
    for (int i = tid; i < 1024; i += 256)
        sB[i] = (i == 0) ? 0 : sA[i-1];
    __syncthreads();
    #pragma unroll
    for (int j = 0; j < 16; j++) {
        int qi = tid + j*256;
        int slot = atomicAdd(&sB[g_key[b*QPB + qi]], 1);
        g_qperm[b*QPB + slot] = qi;
    }
}

// ---------------- grid-accelerated exact top-4 NN --------------------------
#define INS(dd, ii) { \
    bool c3 = (dd) < d3, c2 = (dd) < d2, c1 = (dd) < d1, c0 = (dd) < d0; \
    d3 = c3 ? (c2 ? d2 : (dd)) : d3;  i3 = c3 ? (c2 ? i2 : (ii)) : i3; \
    d2 = c2 ? (c1 ? d1 : (dd)) : d2;  i2 = c2 ? (c1 ? i1 : (ii)) : i2; \
    d1 = c1 ? (c0 ? d0 : (dd)) : d1;  i1 = c1 ? (c0 ? i0 : (ii)) : i1; \
    d0 = c0 ? (dd) : d0;              i0 = c0 ? (ii) : i0; }

__global__ void knn_k() {
    __shared__ float4 sPts[LB];
    __shared__ int    sIdx[LB];
    __shared__ int    sStart[NCELL + 1];
    const int b = blockIdx.y;
    const int n = b & (NB - 1);         // ref set = rp[b % N] (jnp.tile quirk)
    const int tid = threadIdx.x;

    for (int i = tid; i < LB; i += 256) {
        sPts[i] = g_refPts[n][i];
        sIdx[i] = g_refIdx[n][i];
    }
    for (int i = tid; i <= NCELL; i += 256) sStart[i] = g_cellStart[n][i];
    __syncthreads();

    const int pos = blockIdx.x*256 + tid;            // sorted position
    const int qi = g_qperm[b*QPB + pos];
    const int q = b*QPB + qi;
    float4 s = g_sl[q];

    const int cx = cellClamp(s.x), cy = cellClamp(s.y), cz = cellClamp(s.z);
    float ox = fmaxf(fmaxf(-s.x, s.x - 1.f), 0.f);
    float oy = fmaxf(fmaxf(-s.y, s.y - 1.f), 0.f);
    float oz = fmaxf(fmaxf(-s.z, s.z - 1.f), 0.f);
    const float ood2 = ox*ox + oy*oy + oz*oz;
    const float h = 1.f / (float)GD;

    float d0 = 3.4e38f, d1 = 3.4e38f, d2 = 3.4e38f, d3 = 3.4e38f;
    int   i0 = 0, i1 = 0, i2 = 0, i3 = 0;

    for (int r = 0;; r++) {
        int z0 = max(cz - r, 0), z1 = min(cz + r, GD - 1);
        int y0 = max(cy - r, 0), y1 = min(cy + r, GD - 1);
        int x0 = max(cx - r, 0), x1 = min(cx + r, GD - 1);
        for (int z = z0; z <= z1; z++) {
            bool ze = (z == cz - r) || (z == cz + r);
            for (int y = y0; y <= y1; y++) {
                bool fe = ze || (y == cy - r) || (y == cy + r);
                int base = (z*GD + y)*GD;
                if (fe) {
                    // full x row: contiguous point range
                    int p0 = sStart[base + x0], p1 = sStart[base + x1 + 1];
                    for (int p = p0; p < p1; p++) {
                        float4 rr = sPts[p];
                        float dot = fmaf(s.z, rr.z, fmaf(s.y, rr.y, s.x*rr.x));
                        float dd = fmaf(-2.f, dot, s.w + rr.w);
                        INS(dd, p);
                    }
                } else {
                    int xl = cx - r;
                    if (xl >= 0) {
                        int p0 = sStart[base + xl], p1 = sStart[base + xl + 1];
                        for (int p = p0; p < p1; p++) {
                            float4 rr = sPts[p];
                            float dot = fmaf(s.z, rr.z, fmaf(s.y, rr.y, s.x*rr.x));
                            float dd = fmaf(-2.f, dot, s.w + rr.w);
                            INS(dd, p);
                        }
                    }
                    int xr = cx + r;
                    if (xr < GD) {
                        int p0 = sStart[base + xr], p1 = sStart[base + xr + 1];
                        for (int p = p0; p < p1; p++) {
                            float4 rr = sPts[p];
                            float dot = fmaf(s.z, rr.z, fmaf(s.y, rr.y, s.x*rr.x));
                            float dd = fmaf(-2.f, dot, s.w + rr.w);
                            INS(dd, p);
                        }
                    }
                }
            }
        }
        float gap = (float)r * h;
        if (d3 <= fmaf(gap, gap, ood2)) break;                // sound lower bound
        if (x0 == 0 && y0 == 0 && z0 == 0 &&
            x1 == GD-1 && y1 == GD-1 && z1 == GD-1) break;    // full coverage
    }

    float t0 = sqrtf(fmaxf(d0, 1e-12f));
    float t1 = sqrtf(fmaxf(d1, 1e-12f));
    float t2 = sqrtf(fmaxf(d2, 1e-12f));
    float t3 = sqrtf(fmaxf(d3, 1e-12f));
    float w0 = 1.f/(t0 + 1e-8f), w1 = 1.f/(t1 + 1e-8f);
    float w2 = 1.f/(t2 + 1e-8f), w3 = 1.f/(t3 + 1e-8f);
    float scale = g_attw[q] / (w0 + w1 + w2 + w3);

    *(int4*)  (g_idx + 4*q) = make_int4(sIdx[i0], sIdx[i1], sIdx[i2], sIdx[i3]);
    *(float4*)(g_w   + 4*q) = make_float4(w0*scale, w1*scale, w2*scale, w3*scale);
}

// ---------------- gather values + weighted sum (float4 channels) -----------
// thread handles (b,l) and 4 channels; 8 threads cover D=32
__global__ void combine_k() {
    int t = blockIdx.x*256 + threadIdx.x;   // 0..131071
    int g = t >> 3;                          // (b,l): 0..16383
    int c4 = (t & 7) << 2;                   // channel offset 0,4,..28
    int b = g >> 10, l = g & (LB - 1);
    int n_q = b >> 3, h_q = b & 7;           // output placement
    int n_v = b & 1,  h_v = b >> 1;          // value slice (reference quirk)
    const float* vb = g_val + n_v*(LB*EB) + h_v*DB + c4;
    int qb = (b*QPB + l*PB)*KK;
    const int4*   ip = (const int4*)  (g_idx + qb);
    const float4* wp = (const float4*)(g_w   + qb);
    float4 acc = make_float4(0.f, 0.f, 0.f, 0.f);
    #pragma unroll
    for (int j = 0; j < 4; j++) {
        int4   ii = ip[j];
        float4 ww = wp[j];
        float4 v;
        v = *(const float4*)(vb + ii.x*EB);
        acc.x = fmaf(ww.x, v.x, acc.x); acc.y = fmaf(ww.x, v.y, acc.y);
        acc.z = fmaf(ww.x, v.z, acc.z); acc.w = fmaf(ww.x, v.w, acc.w);
        v = *(const float4*)(vb + ii.y*EB);
        acc.x = fmaf(ww.y, v.x, acc.x); acc.y = fmaf(ww.y, v.y, acc.y);
        acc.z = fmaf(ww.y, v.z, acc.z); acc.w = fmaf(ww.y, v.w, acc.w);
        v = *(const float4*)(vb + ii.z*EB);
        acc.x = fmaf(ww.z, v.x, acc.x); acc.y = fmaf(ww.z, v.y, acc.y);
        acc.z = fmaf(ww.z, v.z, acc.z); acc.w = fmaf(ww.z, v.w, acc.w);
        v = *(const float4*)(vb + ii.w*EB);
        acc.x = fmaf(ww.w, v.x, acc.x); acc.y = fmaf(ww.w, v.y, acc.y);
        acc.z = fmaf(ww.w, v.z, acc.z); acc.w = fmaf(ww.w, v.w, acc.w);
    }
    *(float4*)(g_A + (n_q*LB + l)*EB + h_q*DB + c4) = acc;
}

// ---------------------------------------------------------------------------
extern "C" void kernel_launch(void* const* d_in, const int* in_sizes, int n_in,
                              void* d_out, int out_size) {
    const float* q      = (const float*)d_in[0];
    const float* rp     = (const float*)d_in[1];
    const float* W_off  = (const float*)d_in[2];
    const float* b_off  = (const float*)d_in[3];
    const float* W_attn = (const float*)d_in[4];
    const float* b_attn = (const float*)d_in[5];
    const float* W_val  = (const float*)d_in[6];
    const float* b_val  = (const float*)d_in[7];
    const float* W_out  = (const float*)d_in[8];
    const float* b_out  = (const float*)d_in[9];
    float* out = (float*)d_out;

    dim3 blk(256);
    gemm_oa_k <<<dim3(2, 32), blk>>>(q, W_off, b_off, W_attn, b_attn);
    gemm_val_k<<<dim3(4, 32), blk>>>(q, W_val, b_val);
    prep_k    <<<258, blk>>>(rp);            // query prep + ref grid build
    sortq_k   <<<16, blk>>>();
    knn_k     <<<dim3(16, 16), blk>>>();
    combine_k <<<512, blk>>>();
    gemm_out_k<<<dim3(4, 32), blk>>>(W_out, b_out, out);
}

// round 4
// speedup vs baseline: 1.2680x; 1.2680x over previous
#include <cuda_runtime.h>

// Problem constants
#define NB 2
#define LB 1024
#define EB 256
#define HB 8
#define PB 4
#define KK 4
#define DB 32
#define MROWS (NB*LB)        // 2048
#define NH (NB*HB)           // 16
#define QPB (LB*PB)          // 4096 queries per batch-head
#define QTOT (NH*QPB)        // 65536

// ---------------- scratch (device globals) ---------------------------------
__device__ float  g_val [MROWS*EB];
__device__ float  g_off [MROWS*96];
__device__ float  g_attn[MROWS*32];
__device__ float  g_attw[QTOT];
__device__ float4 g_sl  [QTOT];             // sampling loc (x,y,z,|s|^2)
__device__ int    g_key [QTOT];             // Morton cell per query (0..511)
__device__ int    g_qperm[QTOT];            // per-b permutation (Morton sorted)
__device__ int    g_idx [QTOT*KK];
__device__ float  g_w   [QTOT*KK];
__device__ float  g_A   [MROWS*EB];

// ---------------- packed f32x2 helpers (Blackwell) --------------------------
typedef unsigned long long u64;
__device__ __forceinline__ u64 pk(float lo, float hi) {
    u64 v; asm("mov.b64 %0, {%1, %2};" : "=l"(v) : "f"(lo), "f"(hi)); return v;
}
__device__ __forceinline__ void upk(u64 v, float& lo, float& hi) {
    asm("mov.b64 {%0, %1}, %2;" : "=f"(lo), "=f"(hi) : "l"(v));
}
__device__ __forceinline__ u64 fma2(u64 a, u64 b, u64 c) {
    u64 d; asm("fma.rn.f32x2 %0, %1, %2, %3;" : "=l"(d) : "l"(a), "l"(b), "l"(c)); return d;
}
__device__ __forceinline__ u64 mul2(u64 a, u64 b) {
    u64 d; asm("mul.rn.f32x2 %0, %1, %2;" : "=l"(d) : "l"(a), "l"(b)); return d;
}
__device__ __forceinline__ u64 add2(u64 a, u64 b) {
    u64 d; asm("add.rn.f32x2 %0, %1, %2;" : "=l"(d) : "l"(a), "l"(b)); return d;
}

// ---------------- generic 64x64 tiled SGEMM with bias ----------------------
__device__ __forceinline__ void sgemm256_body(const float* __restrict__ A,
                                              const float* __restrict__ B,
                                              const float* __restrict__ bias,
                                              float* __restrict__ C) {
    const int K = 256, NC = 256;
    __shared__ float As[16][64];
    __shared__ float Bs[16][68];
    const int tid = threadIdx.x;
    const int tx = tid & 15, ty = tid >> 4;
    const int rowBase = blockIdx.y * 64;
    const int colBase = blockIdx.x * 64;
    float acc[4][4];
    #pragma unroll
    for (int i = 0; i < 4; i++)
        #pragma unroll
        for (int j = 0; j < 4; j++) acc[i][j] = 0.f;

    for (int k0 = 0; k0 < K; k0 += 16) {
        #pragma unroll
        for (int i = 0; i < 4; i++) {
            int idx = tid + i*256;
            int m = idx >> 4, k = idx & 15;
            As[k][m] = A[(rowBase + m)*K + k0 + k];
        }
        #pragma unroll
        for (int i = 0; i < 4; i++) {
            int idx = tid + i*256;
            int k = idx >> 6, n = idx & 63;
            Bs[k][n] = B[(k0 + k)*NC + colBase + n];
        }
        __syncthreads();
        #pragma unroll
        for (int kk = 0; kk < 16; kk++) {
            float4 av = *(const float4*)&As[kk][ty*4];
            float4 bv = *(const float4*)&Bs[kk][tx*4];
            float a[4] = {av.x, av.y, av.z, av.w};
            float b[4] = {bv.x, bv.y, bv.z, bv.w};
            #pragma unroll
            for (int i = 0; i < 4; i++)
                #pragma unroll
                for (int j = 0; j < 4; j++)
                    acc[i][j] = fmaf(a[i], b[j], acc[i][j]);
        }
        __syncthreads();
    }
    #pragma unroll
    for (int i = 0; i < 4; i++) {
        int gm = rowBase + ty*4 + i;
        #pragma unroll
        for (int j = 0; j < 4; j++) {
            int gn = colBase + tx*4 + j;
            C[gm*NC + gn] = acc[i][j] + bias[gn];
        }
    }
}

__global__ void gemm_val_k(const float* A, const float* B, const float* bias) {
    sgemm256_body(A, B, bias, g_val);
}
__global__ void gemm_out_k(const float* B, const float* bias, float* C) {
    sgemm256_body(g_A, B, bias, C);
}

// Merged off(96) + attn(32) projection: 128 virtual columns
__global__ void gemm_oa_k(const float* __restrict__ A,
                          const float* __restrict__ W_off,  const float* __restrict__ b_off,
                          const float* __restrict__ W_attn, const float* __restrict__ b_attn) {
    const int K = 256;
    __shared__ float As[16][64];
    __shared__ float Bs[16][68];
    const int tid = threadIdx.x;
    const int tx = tid & 15, ty = tid >> 4;
    const int rowBase = blockIdx.y * 64;
    const int colBase = blockIdx.x * 64;   // 0 or 64
    float acc[4][4];
    #pragma unroll
    for (int i = 0; i < 4; i++)
        #pragma unroll
        for (int j = 0; j < 4; j++) acc[i][j] = 0.f;

    for (int k0 = 0; k0 < K; k0 += 16) {
        #pragma unroll
        for (int i = 0; i < 4; i++) {
            int idx = tid + i*256;
            int m = idx >> 4, k = idx & 15;
            As[k][m] = A[(rowBase + m)*K + k0 + k];
        }
        #pragma unroll
        for (int i = 0; i < 4; i++) {
            int idx = tid + i*256;
            int k = idx >> 6, n = idx & 63;
            int gn = colBase + n;
            int gk = k0 + k;
            Bs[k][n] = (gn < 96) ? W_off[gk*96 + gn] : W_attn[gk*32 + (gn - 96)];
        }
        __syncthreads();
        #pragma unroll
        for (int kk = 0; kk < 16; kk++) {
            float4 av = *(const float4*)&As[kk][ty*4];
            float4 bv = *(const float4*)&Bs[kk][tx*4];
            float a[4] = {av.x, av.y, av.z, av.w};
            float b[4] = {bv.x, bv.y, bv.z, bv.w};
            #pragma unroll
            for (int i = 0; i < 4; i++)
                #pragma unroll
                for (int j = 0; j < 4; j++)
                    acc[i][j] = fmaf(a[i], b[j], acc[i][j]);
        }
        __syncthreads();
    }
    #pragma unroll
    for (int i = 0; i < 4; i++) {
        int gm = rowBase + ty*4 + i;
        #pragma unroll
        for (int j = 0; j < 4; j++) {
            int gn = colBase + tx*4 + j;
            if (gn < 96) g_off[gm*96 + gn]         = acc[i][j] + b_off[gn];
            else         g_attn[gm*32 + (gn - 96)] = acc[i][j] + b_attn[gn - 96];
        }
    }
}

// ---------------- query prep: softmax + sampling loc + Morton key ----------
__device__ __forceinline__ int spread3(int x) {        // 3-bit spread
    return (x & 1) | ((x & 2) << 2) | ((x & 4) << 4);
}
__device__ __forceinline__ int cell8(float v) {
    int c = (int)floorf(v * 8.f);
    return min(max(c, 0), 7);
}

__global__ void prep_k(const float* __restrict__ rp) {
    const int q = blockIdx.x*256 + threadIdx.x;
    const int b = q >> 12;
    const int qi = q & (QPB - 1);
    const int l = qi >> 2, p = qi & 3;
    const int n = b >> 3, h = b & 7;
    const int m = n*LB + l;

    float x = g_attn[m*32 + h*4 + p];
    float mx = x;
    mx = fmaxf(mx, __shfl_xor_sync(0xffffffffu, mx, 1));
    mx = fmaxf(mx, __shfl_xor_sync(0xffffffffu, mx, 2));
    float e = expf(x - mx);
    float se = e;
    se += __shfl_xor_sync(0xffffffffu, se, 1);
    se += __shfl_xor_sync(0xffffffffu, se, 2);
    g_attw[q] = e / se;

    float rx = rp[m*3], ry = rp[m*3+1], rz = rp[m*3+2];
    const float* of = g_off + m*96 + h*12 + p*3;
    float sx = rx + of[0], sy = ry + of[1], sz = rz + of[2];
    g_sl[q] = make_float4(sx, sy, sz, sx*sx + sy*sy + sz*sz);
    g_key[q] = spread3(cell8(sx)) | (spread3(cell8(sy)) << 1) | (spread3(cell8(sz)) << 2);
}

// ---------------- per-b counting sort by Morton key (512 bins) -------------
__global__ void sortq_k() {
    __shared__ int cnt[512];
    __shared__ int bstart[512];
    __shared__ int wsum[8];
    const int b = blockIdx.x, tid = threadIdx.x;
    const int lane = tid & 31, w = tid >> 5;

    cnt[tid] = 0; cnt[tid + 256] = 0;
    __syncthreads();
    #pragma unroll
    for (int j = 0; j < 16; j++)
        atomicAdd(&cnt[g_key[b*QPB + tid + j*256]], 1);
    __syncthreads();

    int c0 = cnt[2*tid], c1 = cnt[2*tid + 1];
    int s = c0 + c1;
    int v = s;
    #pragma unroll
    for (int off = 1; off < 32; off <<= 1) {
        int u = __shfl_up_sync(0xffffffffu, v, off);
        if (lane >= off) v += u;
    }
    if (lane == 31) wsum[w] = v;
    __syncthreads();
    if (tid == 0) {
        int acc = 0;
        #pragma unroll
        for (int i = 0; i < 8; i++) { int t = wsum[i]; wsum[i] = acc; acc += t; }
    }
    __syncthreads();
    int excl = v - s + wsum[w];
    bstart[2*tid]     = excl;
    bstart[2*tid + 1] = excl + c0;
    __syncthreads();

    #pragma unroll
    for (int j = 0; j < 16; j++) {
        int qi = tid + j*256;
        int slot = atomicAdd(&bstart[g_key[b*QPB + qi]], 1);
        g_qperm[b*QPB + slot] = qi;
    }
}

// ---------------- brute-force top-4 NN, Morton-coherent warps --------------
#define INS(dd, ii) { \
    bool c3 = (dd) < d3, c2 = (dd) < d2, c1 = (dd) < d1, c0 = (dd) < d0; \
    d3 = c3 ? (c2 ? d2 : (dd)) : d3;  i3 = c3 ? (c2 ? i2 : (ii)) : i3; \
    d2 = c2 ? (c1 ? d1 : (dd)) : d2;  i2 = c2 ? (c1 ? i1 : (ii)) : i2; \
    d1 = c1 ? (c0 ? d0 : (dd)) : d1;  i1 = c1 ? (c0 ? i0 : (ii)) : i1; \
    d0 = c0 ? (dd) : d0;              i0 = c0 ? (ii) : i0; }

__global__ void knn_k(const float* __restrict__ rp) {
    // refs stored as pair-SoA: sXY[j]=(x0,x1,y0,y1), sZW[j]=(z0,z1,w0,w1)
    __shared__ float4 sXY[LB/2];
    __shared__ float4 sZW[LB/2];
    const int b = blockIdx.y;                         // 0..15 (= n*8+h)
    const float* rpb = rp + (b & (NB-1)) * LB * 3;    // ref set = rp[b % N]
    for (int i = threadIdx.x; i < LB; i += 256) {
        float x = rpb[3*i], y = rpb[3*i+1], z = rpb[3*i+2];
        int j = i >> 1, s = i & 1;
        float* xy = (float*)&sXY[j];
        float* zw = (float*)&sZW[j];
        xy[s] = x;  xy[2+s] = y;
        zw[s] = z;  zw[2+s] = x*x + y*y + z*z;
    }
    __syncthreads();

    const int pos = blockIdx.x*256 + threadIdx.x;     // Morton-sorted position
    const int qi = g_qperm[b*QPB + pos];
    const int q = b*QPB + qi;
    float4 s = g_sl[q];

    const u64 sx2 = pk(s.x, s.x), sy2 = pk(s.y, s.y), sz2 = pk(s.z, s.z), sw2 = pk(s.w, s.w);
    const u64 m2 = pk(-2.f, -2.f);

    float d0 = 3.4e38f, d1 = 3.4e38f, d2 = 3.4e38f, d3 = 3.4e38f;
    int   i0 = 0, i1 = 0, i2 = 0, i3 = 0;

    #pragma unroll 4
    for (int j = 0; j < LB/2; j++) {
        float4 xy = sXY[j];
        float4 zw = sZW[j];
        u64 dot = mul2(pk(xy.x, xy.y), sx2);
        dot = fma2(pk(xy.z, xy.w), sy2, dot);
        dot = fma2(pk(zw.x, zw.y), sz2, dot);
        u64 dd2 = fma2(dot, m2, add2(pk(zw.z, zw.w), sw2));
        float lo, hi; upk(dd2, lo, hi);
        if (fminf(lo, hi) < d3) {
            INS(lo, 2*j);
            INS(hi, 2*j + 1);
        }
    }

    float t0 = sqrtf(fmaxf(d0, 1e-12f));
    float t1 = sqrtf(fmaxf(d1, 1e-12f));
    float t2 = sqrtf(fmaxf(d2, 1e-12f));
    float t3 = sqrtf(fmaxf(d3, 1e-12f));
    float w0 = 1.f/(t0 + 1e-8f), w1 = 1.f/(t1 + 1e-8f);
    float w2 = 1.f/(t2 + 1e-8f), w3 = 1.f/(t3 + 1e-8f);
    float scale = g_attw[q] / (w0 + w1 + w2 + w3);

    *(int4*)  (g_idx + 4*q) = make_int4(i0, i1, i2, i3);
    *(float4*)(g_w   + 4*q) = make_float4(w0*scale, w1*scale, w2*scale, w3*scale);
}

// ---------------- gather values + weighted sum (float4 channels) -----------
__global__ void combine_k() {
    int t = blockIdx.x*256 + threadIdx.x;   // 0..131071
    int g = t >> 3;                          // (b,l): 0..16383
    int c4 = (t & 7) << 2;                   // channel offset 0,4,..28
    int b = g >> 10, l = g & (LB - 1);
    int n_q = b >> 3, h_q = b & 7;           // output placement
    int n_v = b & 1,  h_v = b >> 1;          // value slice (reference quirk)
    const float* vb = g_val + n_v*(LB*EB) + h_v*DB + c4;
    int qb = (b*QPB + l*PB)*KK;
    const int4*   ip = (const int4*)  (g_idx + qb);
    const float4* wp = (const float4*)(g_w   + qb);
    float4 acc = make_float4(0.f, 0.f, 0.f, 0.f);
    #pragma unroll
    for (int j = 0; j < 4; j++) {
        int4   ii = ip[j];
        float4 ww = wp[j];
        float4 v;
        v = *(const float4*)(vb + ii.x*EB);
        acc.x = fmaf(ww.x, v.x, acc.x); acc.y = fmaf(ww.x, v.y, acc.y);
        acc.z = fmaf(ww.x, v.z, acc.z); acc.w = fmaf(ww.x, v.w, acc.w);
        v = *(const float4*)(vb + ii.y*EB);
        acc.x = fmaf(ww.y, v.x, acc.x); acc.y = fmaf(ww.y, v.y, acc.y);
        acc.z = fmaf(ww.y, v.z, acc.z); acc.w = fmaf(ww.y, v.w, acc.w);
        v = *(const float4*)(vb + ii.z*EB);
        acc.x = fmaf(ww.z, v.x, acc.x); acc.y = fmaf(ww.z, v.y, acc.y);
        acc.z = fmaf(ww.z, v.z, acc.z); acc.w = fmaf(ww.z, v.w, acc.w);
        v = *(const float4*)(vb + ii.w*EB);
        acc.x = fmaf(ww.w, v.x, acc.x); acc.y = fmaf(ww.w, v.y, acc.y);
        acc.z = fmaf(ww.w, v.z, acc.z); acc.w = fmaf(ww.w, v.w, acc.w);
    }
    *(float4*)(g_A + (n_q*LB + l)*EB + h_q*DB + c4) = acc;
}

// ---------------------------------------------------------------------------
extern "C" void kernel_launch(void* const* d_in, const int* in_sizes, int n_in,
                              void* d_out, int out_size) {
    const float* q      = (const float*)d_in[0];
    const float* rp     = (const float*)d_in[1];
    const float* W_off  = (const float*)d_in[2];
    const float* b_off  = (const float*)d_in[3];
    const float* W_attn = (const float*)d_in[4];
    const float* b_attn = (const float*)d_in[5];
    const float* W_val  = (const float*)d_in[6];
    const float* b_val  = (const float*)d_in[7];
    const float* W_out  = (const float*)d_in[8];
    const float* b_out  = (const float*)d_in[9];
    float* out = (float*)d_out;

    dim3 blk(256);
    gemm_oa_k <<<dim3(2, 32), blk>>>(q, W_off, b_off, W_attn, b_attn);
    gemm_val_k<<<dim3(4, 32), blk>>>(q, W_val, b_val);
    prep_k    <<<256, blk>>>(rp);
    sortq_k   <<<16, blk>>>();
    knn_k     <<<dim3(16, 16), blk>>>(rp);
    combine_k <<<512, blk>>>();
    gemm_out_k<<<dim3(4, 32), blk>>>(W_out, b_out, out);
}